// round 5
// baseline (speedup 1.0000x reference)
#include <cuda_runtime.h>
#include <math_constants.h>
#include <stdint.h>

#define LMAX 100000
#define IMAX 10000
#define NMAX 1000000
#define CC 128

// ---------------- static device scratch ----------------
__device__ int      g_cnt[LMAX];
__device__ float    g_sum[LMAX * 3];
__device__ float    g_centroid[LMAX * 3];
__device__ int      g_off[LMAX + 1];
__device__ int      g_cursor[LMAX];
__device__ int      g_pids[NMAX];
__device__ int      g_plocal[NMAX];
__device__ float    g_shape_max[(size_t)LMAX * CC];
__device__ float    g_locals_feat[(size_t)LMAX * CC];
__device__ int      g_cnt_i[IMAX];
__device__ unsigned g_gkeys[(size_t)IMAX * CC];
__device__ float    g_gtlc[IMAX * 3];
__device__ float    g_globals[(size_t)IMAX * CC];

// order-preserving float<->uint key for atomicMax on signed floats
__device__ __forceinline__ unsigned fkey(float f) {
    unsigned b = __float_as_uint(f);
    return (b & 0x80000000u) ? ~b : (b | 0x80000000u);
}
__device__ __forceinline__ float funkey(unsigned k) {
    return (k & 0x80000000u) ? __uint_as_float(k & 0x7fffffffu) : __uint_as_float(~k);
}

// ---------------- init ----------------
__global__ void k_init(int L, int I) {
    int idx = blockIdx.x * blockDim.x + threadIdx.x;
    if (idx < L * CC) g_shape_max[idx] = 0.f;
    if (idx < I * CC) g_gkeys[idx] = 0x007fffffu;   // fkey(-inf)
    if (idx < 3 * L) g_sum[idx] = 0.f;
    if (idx < L) { g_cnt[idx] = 0; g_cursor[idx] = 0; }
    if (idx < I) g_cnt_i[idx] = 0;
}

// ---------------- centroid count + sum ----------------
__global__ void k_count(const float* __restrict__ xyz, const int* __restrict__ l2f, int n) {
    int i = blockIdx.x * blockDim.x + threadIdx.x;
    if (i >= n) return;
    int l = l2f[i];
    atomicAdd(&g_cnt[l], 1);
    atomicAdd(&g_sum[l * 3 + 0], xyz[i * 3 + 0]);
    atomicAdd(&g_sum[l * 3 + 1], xyz[i * 3 + 1]);
    atomicAdd(&g_sum[l * 3 + 2], xyz[i * 3 + 2]);
}

__global__ void k_centroid(int L) {
    int l = blockIdx.x * blockDim.x + threadIdx.x;
    if (l >= L) return;
    float inv = 1.f / fmaxf((float)g_cnt[l], 1.f);
    g_centroid[l * 3 + 0] = g_sum[l * 3 + 0] * inv;
    g_centroid[l * 3 + 1] = g_sum[l * 3 + 1] * inv;
    g_centroid[l * 3 + 2] = g_sum[l * 3 + 2] * inv;
}

// ---------------- exclusive scan over g_cnt (one block) ----------------
__global__ void k_scan(int L) {
    __shared__ int sh[1024];
    __shared__ int carry_s;
    int tid = threadIdx.x;
    if (tid == 0) carry_s = 0;
    __syncthreads();
    for (int base = 0; base < L; base += 1024) {
        int i = base + tid;
        int v = (i < L) ? g_cnt[i] : 0;
        sh[tid] = v;
        __syncthreads();
        for (int s = 1; s < 1024; s <<= 1) {
            int t = (tid >= s) ? sh[tid - s] : 0;
            __syncthreads();
            sh[tid] += t;
            __syncthreads();
        }
        int carry = carry_s;
        if (i < L) g_off[i] = carry + sh[tid] - v;
        __syncthreads();
        if (tid == 1023) carry_s = carry + sh[1023];
        __syncthreads();
    }
    if (tid == 0) g_off[L] = carry_s;
}

// ---------------- CSR scatter ----------------
__global__ void k_csr(const int* __restrict__ l2f, int n) {
    int i = blockIdx.x * blockDim.x + threadIdx.x;
    if (i >= n) return;
    int l = l2f[i];
    int pos = atomicAdd(&g_cursor[l], 1);
    int slot = g_off[l] + pos;
    g_pids[slot] = i;
    g_plocal[slot] = l;
}

// ---------------- shape MLP on CSR-ordered points + segmented max ----------------
// smem: hT/outS[128*128] | W2s[128*128] | W1s[384] | b1s[128] | b2s[128] | lidS[128 ints]
#define SH_SHAPE ((16384 + 16384 + 384 + 128 + 128) * 4 + 128 * 4)

__global__ __launch_bounds__(256) void k_shape(
    const float* __restrict__ xyz,
    const float* __restrict__ W1, const float* __restrict__ b1,
    const float* __restrict__ W2, const float* __restrict__ b2, int n)
{
    extern __shared__ float sm[];
    float* hT  = sm;            // [k][p]
    float* W2s = sm + 16384;    // [k][c]
    float* W1s = sm + 32768;    // [dim][k] = W1[dim*128+k]
    float* b1s = sm + 33152;
    float* b2s = sm + 33280;
    int*  lidS = (int*)(sm + 33408);

    int tid = threadIdx.x;
    int tile0 = blockIdx.x * 128;

    for (int i = tid; i < 16384; i += 256) W2s[i] = W2[i];
    for (int i = tid; i < 384; i += 256) W1s[i] = W1[i];
    if (tid < 128) { b1s[tid] = b1[tid]; b2s[tid] = b2[tid]; }
    __syncthreads();

    // hidden layer: 2 threads per point, 64 hidden units each
    {
        int p = tid & 127, half = tid >> 7;
        int row = tile0 + p;
        float cx = 0.f, cy = 0.f, cz = 0.f;
        int l = -1;
        bool valid = (row < n);
        if (valid) {
            int pid = g_pids[row];
            l = g_plocal[row];
            cx = xyz[pid * 3 + 0] - g_centroid[l * 3 + 0];
            cy = xyz[pid * 3 + 1] - g_centroid[l * 3 + 1];
            cz = xyz[pid * 3 + 2] - g_centroid[l * 3 + 2];
        }
        if (half == 0) lidS[p] = l;
        int k0 = half * 64;
        #pragma unroll 8
        for (int k = k0; k < k0 + 64; k++) {
            float h = fmaf(cx, W1s[k], fmaf(cy, W1s[128 + k], fmaf(cz, W1s[256 + k], b1s[k])));
            hT[k * 128 + p] = valid ? fmaxf(h, 0.f) : 0.f;
        }
    }
    __syncthreads();

    // 128x128x128 fp32 GEMM, 8x8 register tile
    int c0 = (tid & 15) << 3;
    int p0 = (tid >> 4) << 3;
    float acc[8][8];
    #pragma unroll
    for (int i = 0; i < 8; i++)
        #pragma unroll
        for (int j = 0; j < 8; j++) acc[i][j] = 0.f;

    #pragma unroll 4
    for (int k = 0; k < 128; k++) {
        float4 a0 = *(const float4*)&hT[k * 128 + p0];
        float4 a1 = *(const float4*)&hT[k * 128 + p0 + 4];
        float4 w0 = *(const float4*)&W2s[k * 128 + c0];
        float4 w1 = *(const float4*)&W2s[k * 128 + c0 + 4];
        float a[8] = {a0.x, a0.y, a0.z, a0.w, a1.x, a1.y, a1.z, a1.w};
        float w[8] = {w0.x, w0.y, w0.z, w0.w, w1.x, w1.y, w1.z, w1.w};
        #pragma unroll
        for (int i = 0; i < 8; i++)
            #pragma unroll
            for (int j = 0; j < 8; j++) acc[i][j] = fmaf(a[i], w[j], acc[i][j]);
    }
    __syncthreads();

    float* outS = hT;  // reuse
    #pragma unroll
    for (int i = 0; i < 8; i++)
        #pragma unroll
        for (int j = 0; j < 8; j++)
            outS[(p0 + i) * 128 + c0 + j] = fmaxf(acc[i][j] + b2s[c0 + j], 0.f);
    __syncthreads();

    // segmented max over sorted locals: interior segments store, boundary atomic.
    // values >= 0 (post-relu) with init 0, so int atomicMax on float bits is valid.
    if (tid < 128) {
        int c = tid;
        int cur = -2, s = 0;
        float m = 0.f;
        for (int r = 0; r < 128; r++) {
            int l = lidS[r];
            float v = outS[r * 128 + c];
            if (l != cur) {
                if (cur >= 0) {
                    float* dst = &g_shape_max[(size_t)cur * CC + c];
                    if (s > 0) *dst = m;
                    else atomicMax((int*)dst, __float_as_int(m));
                }
                cur = l; m = v; s = r;
            } else m = fmaxf(m, v);
        }
        if (cur >= 0)
            atomicMax((int*)&g_shape_max[(size_t)cur * CC + c], __float_as_int(m));
    }
}

// ---------------- fg_feat segmax + locals_feat + global key-max ----------------
__global__ void k_featmax(const float* __restrict__ feat, const int* __restrict__ i2l, int L) {
    int gt = blockIdx.x * blockDim.x + threadIdx.x;
    int w = gt >> 5, lane = gt & 31;
    if (w >= L) return;
    int s = g_off[w], e = g_off[w + 1];
    float m0 = -CUDART_INF_F, m1 = m0, m2 = m0, m3 = m0;
    for (int p = s; p < e; p++) {
        const float* row = feat + (size_t)g_pids[p] * CC;
        m0 = fmaxf(m0, row[lane]);
        m1 = fmaxf(m1, row[lane + 32]);
        m2 = fmaxf(m2, row[lane + 64]);
        m3 = fmaxf(m3, row[lane + 96]);
    }
    if (e <= s) { m0 = m1 = m2 = m3 = 0.f; }
    size_t base = (size_t)w * CC;
    float v0 = m0 + g_shape_max[base + lane];
    float v1 = m1 + g_shape_max[base + lane + 32];
    float v2 = m2 + g_shape_max[base + lane + 64];
    float v3 = m3 + g_shape_max[base + lane + 96];
    g_locals_feat[base + lane]      = v0;
    g_locals_feat[base + lane + 32] = v1;
    g_locals_feat[base + lane + 64] = v2;
    g_locals_feat[base + lane + 96] = v3;
    int inst = i2l[w];
    size_t gb = (size_t)inst * CC;
    atomicMax(&g_gkeys[gb + lane],      fkey(v0));
    atomicMax(&g_gkeys[gb + lane + 32], fkey(v1));
    atomicMax(&g_gkeys[gb + lane + 64], fkey(v2));
    atomicMax(&g_gkeys[gb + lane + 96], fkey(v3));
    if (lane == 0) atomicAdd(&g_cnt_i[inst], 1);
}

// ---------------- finalize globals + target centers ----------------
__global__ void k_gfin(const int* __restrict__ ils, int I) {
    int idx = blockIdx.x * blockDim.x + threadIdx.x;
    if (idx < I * CC) {
        int i = idx >> 7;
        g_globals[idx] = (g_cnt_i[i] > 0) ? funkey(g_gkeys[idx]) : 0.f;
    }
    if (idx < I * 3) {
        int i = idx / 3, d = idx % 3;
        g_gtlc[idx] = g_centroid[ils[i] * 3 + d];
    }
}

// ---------------- locals MLP (262->128 relu ->128 relu) + decoder (->7) ----------------
// smem: fS[262*128] (reused as hT[128*128] then foS[128*133]) | b1L | b2L | wdS[1032] | ilS
#define KF 262
#define SH_MLP2 ((KF * 128 + 128 + 128 + 1032) * 4 + 128 * 4)

__global__ __launch_bounds__(256) void k_mlp2(
    const float* __restrict__ W1, const float* __restrict__ b1,
    const float* __restrict__ W2, const float* __restrict__ b2,
    const float* __restrict__ Wd, const float* __restrict__ bd,
    const int* __restrict__ i2l,
    float* __restrict__ out_tf, float* __restrict__ out_fo, int L)
{
    extern __shared__ float sm[];
    float* fS  = sm;                       // [k][p], k<262
    float* b1L = sm + KF * 128;            // 128
    float* b2L = b1L + 128;                // 128
    float* wdS = b2L + 128;                // [c][8] padded, 1024 + bdec at +1024
    float* bdS = wdS + 1024;               // 8
    int*  ilS  = (int*)(wdS + 1032);       // 128

    int tid = threadIdx.x;
    int block0 = blockIdx.x * 128;

    if (tid < 128) {
        b1L[tid] = b1[tid];
        b2L[tid] = b2[tid];
        int l = block0 + tid;
        ilS[tid] = (l < L) ? i2l[l] : 0;
    }
    for (int idx = tid; idx < 128 * 7; idx += 256)
        wdS[(idx / 7) * 8 + (idx % 7)] = Wd[idx];
    if (tid < 7) bdS[tid] = bd[tid];
    __syncthreads();

    // assemble feat [k][p]
    for (int idx = tid; idx < KF * 128; idx += 256) {
        int k = idx >> 7, p = idx & 127;
        int l = block0 + p;
        float v = 0.f;
        if (l < L) {
            int inst = ilS[p];
            if (k < 128)       v = g_locals_feat[(size_t)l * CC + k];
            else if (k < 256)  v = g_globals[(size_t)inst * CC + (k - 128)];
            else if (k < 259)  v = g_centroid[l * 3 + (k - 256)];
            else               v = g_gtlc[inst * 3 + (k - 259)];
        }
        fS[k * 128 + p] = v;
    }
    __syncthreads();

    int h0 = (tid & 15) << 3;   // GEMM1 output-channel tile (hidden)
    int p0 = (tid >> 4) << 3;   // local tile
    float acc[8][8];
    #pragma unroll
    for (int i = 0; i < 8; i++)
        #pragma unroll
        for (int j = 0; j < 8; j++) acc[i][j] = 0.f;

    #pragma unroll 2
    for (int k = 0; k < KF; k++) {
        float4 a0 = *(const float4*)&fS[k * 128 + p0];
        float4 a1 = *(const float4*)&fS[k * 128 + p0 + 4];
        float4 w0 = *(const float4*)&W1[k * 128 + h0];
        float4 w1 = *(const float4*)&W1[k * 128 + h0 + 4];
        float a[8] = {a0.x, a0.y, a0.z, a0.w, a1.x, a1.y, a1.z, a1.w};
        float w[8] = {w0.x, w0.y, w0.z, w0.w, w1.x, w1.y, w1.z, w1.w};
        #pragma unroll
        for (int i = 0; i < 8; i++)
            #pragma unroll
            for (int j = 0; j < 8; j++) acc[i][j] = fmaf(a[i], w[j], acc[i][j]);
    }
    __syncthreads();  // fS reads done -> reuse as hT

    float* hT = fS;
    #pragma unroll
    for (int i = 0; i < 8; i++)
        #pragma unroll
        for (int j = 0; j < 8; j++)
            hT[(h0 + j) * 128 + p0 + i] = fmaxf(acc[i][j] + b1L[h0 + j], 0.f);
    __syncthreads();

    // GEMM2: 128x128x128, W2 from L2
    int c0 = h0;
    #pragma unroll
    for (int i = 0; i < 8; i++)
        #pragma unroll
        for (int j = 0; j < 8; j++) acc[i][j] = 0.f;

    #pragma unroll 4
    for (int k = 0; k < 128; k++) {
        float4 a0 = *(const float4*)&hT[k * 128 + p0];
        float4 a1 = *(const float4*)&hT[k * 128 + p0 + 4];
        float4 w0 = *(const float4*)&W2[k * 128 + c0];
        float4 w1 = *(const float4*)&W2[k * 128 + c0 + 4];
        float a[8] = {a0.x, a0.y, a0.z, a0.w, a1.x, a1.y, a1.z, a1.w};
        float w[8] = {w0.x, w0.y, w0.z, w0.w, w1.x, w1.y, w1.z, w1.w};
        #pragma unroll
        for (int i = 0; i < 8; i++)
            #pragma unroll
            for (int j = 0; j < 8; j++) acc[i][j] = fmaf(a[i], w[j], acc[i][j]);
    }

    // relu + b2, write feat_out to gmem; keep in regs for dec
    #pragma unroll
    for (int i = 0; i < 8; i++) {
        int l = block0 + p0 + i;
        #pragma unroll
        for (int j = 0; j < 8; j++) {
            acc[i][j] = fmaxf(acc[i][j] + b2L[c0 + j], 0.f);
            if (l < L) out_fo[(size_t)l * CC + c0 + j] = acc[i][j];
        }
    }
    __syncthreads();  // hT reads done -> reuse as foS

    float* foS = fS;  // [p][133]
    #pragma unroll
    for (int i = 0; i < 8; i++)
        #pragma unroll
        for (int j = 0; j < 8; j++)
            foS[(p0 + i) * 133 + c0 + j] = acc[i][j];
    __syncthreads();

    // decoder: 128 threads, one local each, 7 outputs
    if (tid < 128) {
        int l = block0 + tid;
        if (l < L) {
            float s[7];
            #pragma unroll
            for (int j = 0; j < 7; j++) s[j] = bdS[j];
            for (int c = 0; c < 128; c++) {
                float f = foS[tid * 133 + c];
                #pragma unroll
                for (int j = 0; j < 7; j++) s[j] = fmaf(f, wdS[c * 8 + j], s[j]);
            }
            #pragma unroll
            for (int j = 0; j < 7; j++) out_tf[(size_t)l * 7 + j] = s[j];
        }
    }
}

// ---------------- launch ----------------
extern "C" void kernel_launch(void* const* d_in, const int* in_sizes, int n_in,
                              void* d_out, int out_size) {
    const float* xyz  = (const float*)d_in[0];
    const float* feat = (const float*)d_in[1];
    const float* W1s_ = (const float*)d_in[2];
    const float* b1s_ = (const float*)d_in[3];
    const float* W2s_ = (const float*)d_in[4];
    const float* b2s_ = (const float*)d_in[5];
    const float* W1l  = (const float*)d_in[6];
    const float* b1l  = (const float*)d_in[7];
    const float* W2l  = (const float*)d_in[8];
    const float* b2l  = (const float*)d_in[9];
    const float* Wd   = (const float*)d_in[10];
    const float* bd   = (const float*)d_in[11];
    const int*   l2f  = (const int*)d_in[12];
    const int*   i2l  = (const int*)d_in[13];
    const int*   ils  = (const int*)d_in[14];

    int n = in_sizes[0] / 3;
    int L = in_sizes[13];
    int I = in_sizes[14];

    float* out_tf = (float*)d_out;
    float* out_fo = (float*)d_out + (size_t)L * 7;

    cudaFuncSetAttribute(k_shape, cudaFuncAttributeMaxDynamicSharedMemorySize, SH_SHAPE);
    cudaFuncSetAttribute(k_mlp2,  cudaFuncAttributeMaxDynamicSharedMemorySize, SH_MLP2);

    k_init<<<(L * CC + 255) / 256, 256>>>(L, I);
    k_count<<<(n + 255) / 256, 256>>>(xyz, l2f, n);
    k_centroid<<<(L + 255) / 256, 256>>>(L);
    k_scan<<<1, 1024>>>(L);
    k_csr<<<(n + 255) / 256, 256>>>(l2f, n);
    k_shape<<<(n + 127) / 128, 256, SH_SHAPE>>>(xyz, W1s_, b1s_, W2s_, b2s_, n);
    k_featmax<<<(L * 32 + 255) / 256, 256>>>(feat, i2l, L);
    k_gfin<<<(I * CC + 255) / 256, 256>>>(ils, I);
    k_mlp2<<<(L + 127) / 128, 256, SH_MLP2>>>(W1l, b1l, W2l, b2l, Wd, bd, i2l, out_tf, out_fo, L);
}

// round 7
// speedup vs baseline: 1.6186x; 1.6186x over previous
#include <cuda_runtime.h>
#include <cuda_fp16.h>
#include <math_constants.h>
#include <stdint.h>

#define LMAX 100000
#define IMAX 10000
#define NMAX 1000000
#define CC 128

// ---------------- static device scratch ----------------
__device__ int      g_cnt[LMAX];
__device__ float    g_sum[LMAX * 3];
__device__ float    g_centroid[LMAX * 3];
__device__ int      g_off[LMAX + 1];
__device__ int      g_cursor[LMAX];
__device__ int      g_pids[NMAX];
__device__ int      g_plocal[NMAX];
__device__ float    g_shape_max[(size_t)LMAX * CC];
__device__ float    g_locals_feat[(size_t)LMAX * CC];
__device__ int      g_cnt_i[IMAX];
__device__ unsigned g_gkeys[(size_t)IMAX * CC];
__device__ float    g_gtlc[IMAX * 3];
__device__ float    g_globals[(size_t)IMAX * CC];
__device__ __half   g_W2t[128 * 128];   // W2 transposed, fp16: g_W2t[c*128+k] = W2[k][c]

// order-preserving float<->uint key for atomicMax on signed floats
__device__ __forceinline__ unsigned fkey(float f) {
    unsigned b = __float_as_uint(f);
    return (b & 0x80000000u) ? ~b : (b | 0x80000000u);
}
__device__ __forceinline__ float funkey(unsigned k) {
    return (k & 0x80000000u) ? __uint_as_float(k & 0x7fffffffu) : __uint_as_float(~k);
}

// ---------------- init ----------------
__global__ void k_init(int L, int I) {
    int idx = blockIdx.x * blockDim.x + threadIdx.x;
    if (idx < L * CC) g_shape_max[idx] = 0.f;
    if (idx < I * CC) g_gkeys[idx] = 0x007fffffu;   // fkey(-inf)
    if (idx < 3 * L) g_sum[idx] = 0.f;
    if (idx < L) { g_cnt[idx] = 0; g_cursor[idx] = 0; }
    if (idx < I) g_cnt_i[idx] = 0;
}

// ---------------- prep: transpose + fp16-convert W2_shape ----------------
__global__ void k_prep(const float* __restrict__ W2) {
    int i = blockIdx.x * blockDim.x + threadIdx.x;
    if (i < 16384) {
        int c = i >> 7, k = i & 127;
        g_W2t[i] = __float2half(W2[k * 128 + c]);
    }
}

// ---------------- centroid count + sum ----------------
__global__ void k_count(const float* __restrict__ xyz, const int* __restrict__ l2f, int n) {
    int i = blockIdx.x * blockDim.x + threadIdx.x;
    if (i >= n) return;
    int l = l2f[i];
    atomicAdd(&g_cnt[l], 1);
    atomicAdd(&g_sum[l * 3 + 0], xyz[i * 3 + 0]);
    atomicAdd(&g_sum[l * 3 + 1], xyz[i * 3 + 1]);
    atomicAdd(&g_sum[l * 3 + 2], xyz[i * 3 + 2]);
}

__global__ void k_centroid(int L) {
    int l = blockIdx.x * blockDim.x + threadIdx.x;
    if (l >= L) return;
    float inv = 1.f / fmaxf((float)g_cnt[l], 1.f);
    g_centroid[l * 3 + 0] = g_sum[l * 3 + 0] * inv;
    g_centroid[l * 3 + 1] = g_sum[l * 3 + 1] * inv;
    g_centroid[l * 3 + 2] = g_sum[l * 3 + 2] * inv;
}

// ---------------- exclusive scan over g_cnt: chunked, one block, warp-shuffle ----------------
__global__ void k_scan(int L) {
    __shared__ int wsum[32];
    int tid = threadIdx.x;                 // 1024 threads
    int chunk = (L + 1023) >> 10;
    int s = tid * chunk;
    int e = s + chunk; if (e > L) e = L;
    if (s > L) s = L;
    int sum = 0;
    for (int i = s; i < e; i++) sum += g_cnt[i];

    int lane = tid & 31, w = tid >> 5;
    int v = sum;
    #pragma unroll
    for (int o = 1; o < 32; o <<= 1) {
        int t = __shfl_up_sync(0xffffffffu, v, o);
        if (lane >= o) v += t;
    }
    if (lane == 31) wsum[w] = v;
    __syncthreads();
    if (w == 0) {
        int x = wsum[lane];
        #pragma unroll
        for (int o = 1; o < 32; o <<= 1) {
            int t = __shfl_up_sync(0xffffffffu, x, o);
            if (lane >= o) x += t;
        }
        wsum[lane] = x;
    }
    __syncthreads();
    int excl = v - sum + (w > 0 ? wsum[w - 1] : 0);
    int run = excl;
    for (int i = s; i < e; i++) { int c = g_cnt[i]; g_off[i] = run; run += c; }
    if (tid == 1023) g_off[L] = run;
}

// ---------------- CSR scatter ----------------
__global__ void k_csr(const int* __restrict__ l2f, int n) {
    int i = blockIdx.x * blockDim.x + threadIdx.x;
    if (i >= n) return;
    int l = l2f[i];
    int pos = atomicAdd(&g_cursor[l], 1);
    int slot = g_off[l] + pos;
    g_pids[slot] = i;
    g_plocal[slot] = l;
}

// ---------------- shape MLP: layer1 fp32 -> fp16, layer2 on tensor cores ----------------
// smem: [hA 128x136 half | W2t 128x136 half]  (69632 B, reused as outS 128x128 f32)
//       then W1s(384f) b1s(128f) b2s(128f) lidS(128i)
#define STRH 136
#define SH_SHAPE (128 * STRH * 2 * 2 + (384 + 128 + 128) * 4 + 128 * 4)

__device__ __forceinline__ void mma16816(float* d, const unsigned* a, unsigned b0, unsigned b1) {
    asm volatile(
        "mma.sync.aligned.m16n8k16.row.col.f32.f16.f16.f32 "
        "{%0,%1,%2,%3}, {%4,%5,%6,%7}, {%8,%9}, {%0,%1,%2,%3};"
        : "+f"(d[0]), "+f"(d[1]), "+f"(d[2]), "+f"(d[3])
        : "r"(a[0]), "r"(a[1]), "r"(a[2]), "r"(a[3]), "r"(b0), "r"(b1));
}

__global__ __launch_bounds__(256) void k_shape(
    const float* __restrict__ xyz,
    const float* __restrict__ W1, const float* __restrict__ b1,
    const float* __restrict__ b2, int n)
{
    extern __shared__ char smraw[];
    __half* hA  = (__half*)smraw;                        // [128][STRH]
    __half* W2t = (__half*)(smraw + 128 * STRH * 2);     // [128][STRH]
    float*  outS = (float*)smraw;                        // reuse, [128][128]
    float*  ext = (float*)(smraw + 128 * STRH * 2 * 2);
    float*  W1s = ext;          // [dim][k]
    float*  b1s = ext + 384;
    float*  b2s = ext + 512;
    int*   lidS = (int*)(ext + 640);

    int tid = threadIdx.x;
    int tile0 = blockIdx.x * 128;

    for (int i = tid; i < 384; i += 256) W1s[i] = W1[i];
    if (tid < 128) { b1s[tid] = b1[tid]; b2s[tid] = b2[tid]; }
    __syncthreads();

    // layer1 (fp32 math, fp16 store) + W2t smem copy, same phase
    {
        int p = tid & 127, hid = tid >> 7;
        int row = tile0 + p;
        float cx = 0.f, cy = 0.f, cz = 0.f;
        int l = -1;
        bool valid = (row < n);
        if (valid) {
            int pid = g_pids[row];
            l = g_plocal[row];
            cx = xyz[pid * 3 + 0] - g_centroid[l * 3 + 0];
            cy = xyz[pid * 3 + 1] - g_centroid[l * 3 + 1];
            cz = xyz[pid * 3 + 2] - g_centroid[l * 3 + 2];
        }
        if (hid == 0) lidS[p] = l;
        int k0 = hid * 64;
        #pragma unroll 8
        for (int k = k0; k < k0 + 64; k += 2) {
            float h0 = fmaf(cx, W1s[k],   fmaf(cy, W1s[128 + k],   fmaf(cz, W1s[256 + k],   b1s[k])));
            float h1 = fmaf(cx, W1s[k+1], fmaf(cy, W1s[128 + k+1], fmaf(cz, W1s[256 + k+1], b1s[k+1])));
            h0 = valid ? fmaxf(h0, 0.f) : 0.f;
            h1 = valid ? fmaxf(h1, 0.f) : 0.f;
            *(__half2*)&hA[p * STRH + k] = __floats2half2_rn(h0, h1);
        }
        // copy W2t (fp16, prepped) into padded smem, 2 halves per iter
        const unsigned* src = (const unsigned*)g_W2t;
        for (int i = tid; i < 8192; i += 256) {
            int c = i >> 6, k2 = (i & 63) << 1;
            *(unsigned*)&W2t[c * STRH + k2] = src[i];
        }
    }
    __syncthreads();

    // tensor-core GEMM: 128x128x128, warps 4(m) x 2(n), warp tile m32 x n64
    int wid = tid >> 5, lane = tid & 31;
    int m0 = (wid >> 1) * 32, n0 = (wid & 1) * 64;
    int g = lane >> 2, t4 = (lane & 3) * 2;

    float acc[2][8][4];
    #pragma unroll
    for (int a = 0; a < 2; a++)
        #pragma unroll
        for (int b_ = 0; b_ < 8; b_++)
            #pragma unroll
            for (int c = 0; c < 4; c++) acc[a][b_][c] = 0.f;

    #pragma unroll
    for (int kk = 0; kk < 128; kk += 16) {
        unsigned afr[2][4];
        #pragma unroll
        for (int mt = 0; mt < 2; mt++) {
            const __half* base = &hA[(m0 + mt * 16 + g) * STRH + kk + t4];
            afr[mt][0] = *(const unsigned*)base;
            afr[mt][1] = *(const unsigned*)(base + 8 * STRH);
            afr[mt][2] = *(const unsigned*)(base + 8);
            afr[mt][3] = *(const unsigned*)(base + 8 * STRH + 8);
        }
        #pragma unroll
        for (int nt = 0; nt < 8; nt++) {
            const __half* bb = &W2t[(n0 + nt * 8 + g) * STRH + kk + t4];
            unsigned b0 = *(const unsigned*)bb;
            unsigned b1v = *(const unsigned*)(bb + 8);
            mma16816(acc[0][nt], afr[0], b0, b1v);
            mma16816(acc[1][nt], afr[1], b0, b1v);
        }
    }
    __syncthreads();   // done reading hA/W2t -> reuse as outS

    // epilogue: relu(acc + b2) -> outS[p][c]
    #pragma unroll
    for (int mt = 0; mt < 2; mt++) {
        #pragma unroll
        for (int nt = 0; nt < 8; nt++) {
            int r0 = m0 + mt * 16 + g;
            int c = n0 + nt * 8 + t4;
            float2 v0, v1;
            v0.x = fmaxf(acc[mt][nt][0] + b2s[c], 0.f);
            v0.y = fmaxf(acc[mt][nt][1] + b2s[c + 1], 0.f);
            v1.x = fmaxf(acc[mt][nt][2] + b2s[c], 0.f);
            v1.y = fmaxf(acc[mt][nt][3] + b2s[c + 1], 0.f);
            *(float2*)&outS[r0 * 128 + c] = v0;
            *(float2*)&outS[(r0 + 8) * 128 + c] = v1;
        }
    }
    __syncthreads();

    // segmented max over sorted locals: interior segments plain-store, boundary atomic.
    // values >= 0 (post-relu) with init 0, so int atomicMax on float bits is valid.
    if (tid < 128) {
        int c = tid;
        int cur = -2, s = 0;
        float m = 0.f;
        for (int r = 0; r < 128; r++) {
            int l = lidS[r];
            float v = outS[r * 128 + c];
            if (l != cur) {
                if (cur >= 0) {
                    float* dst = &g_shape_max[(size_t)cur * CC + c];
                    if (s > 0) *dst = m;
                    else atomicMax((int*)dst, __float_as_int(m));
                }
                cur = l; m = v; s = r;
            } else m = fmaxf(m, v);
        }
        if (cur >= 0)
            atomicMax((int*)&g_shape_max[(size_t)cur * CC + c], __float_as_int(m));
    }
}

// ---------------- fg_feat segmax + locals_feat + global key-max ----------------
__global__ void k_featmax(const float* __restrict__ feat, const int* __restrict__ i2l, int L) {
    int gt = blockIdx.x * blockDim.x + threadIdx.x;
    int w = gt >> 5, lane = gt & 31;
    if (w >= L) return;
    int s = g_off[w], e = g_off[w + 1];
    float m0 = -CUDART_INF_F, m1 = m0, m2 = m0, m3 = m0;
    for (int p = s; p < e; p++) {
        const float* row = feat + (size_t)g_pids[p] * CC;
        m0 = fmaxf(m0, row[lane]);
        m1 = fmaxf(m1, row[lane + 32]);
        m2 = fmaxf(m2, row[lane + 64]);
        m3 = fmaxf(m3, row[lane + 96]);
    }
    if (e <= s) { m0 = m1 = m2 = m3 = 0.f; }
    size_t base = (size_t)w * CC;
    float v0 = m0 + g_shape_max[base + lane];
    float v1 = m1 + g_shape_max[base + lane + 32];
    float v2 = m2 + g_shape_max[base + lane + 64];
    float v3 = m3 + g_shape_max[base + lane + 96];
    g_locals_feat[base + lane]      = v0;
    g_locals_feat[base + lane + 32] = v1;
    g_locals_feat[base + lane + 64] = v2;
    g_locals_feat[base + lane + 96] = v3;
    int inst = i2l[w];
    size_t gb = (size_t)inst * CC;
    atomicMax(&g_gkeys[gb + lane],      fkey(v0));
    atomicMax(&g_gkeys[gb + lane + 32], fkey(v1));
    atomicMax(&g_gkeys[gb + lane + 64], fkey(v2));
    atomicMax(&g_gkeys[gb + lane + 96], fkey(v3));
    if (lane == 0) atomicAdd(&g_cnt_i[inst], 1);
}

// ---------------- finalize globals + target centers ----------------
__global__ void k_gfin(const int* __restrict__ ils, int I) {
    int idx = blockIdx.x * blockDim.x + threadIdx.x;
    if (idx < I * CC) {
        int i = idx >> 7;
        g_globals[idx] = (g_cnt_i[i] > 0) ? funkey(g_gkeys[idx]) : 0.f;
    }
    if (idx < I * 3) {
        int i = idx / 3, d = idx % 3;
        g_gtlc[idx] = g_centroid[ils[i] * 3 + d];
    }
}

// ---------------- locals MLP (262->128 relu ->128 relu) + decoder (->7) ----------------
#define KF 262
#define SH_MLP2 ((KF * 128 + 128 + 128 + 1032) * 4 + 128 * 4)

__global__ __launch_bounds__(256) void k_mlp2(
    const float* __restrict__ W1, const float* __restrict__ b1,
    const float* __restrict__ W2, const float* __restrict__ b2,
    const float* __restrict__ Wd, const float* __restrict__ bd,
    const int* __restrict__ i2l,
    float* __restrict__ out_tf, float* __restrict__ out_fo, int L)
{
    extern __shared__ float sm[];
    float* fS  = sm;                       // [k][p], k<262
    float* b1L = sm + KF * 128;
    float* b2L = b1L + 128;
    float* wdS = b2L + 128;                // [c][8] padded
    float* bdS = wdS + 1024;
    int*  ilS  = (int*)(wdS + 1032);

    int tid = threadIdx.x;
    int block0 = blockIdx.x * 128;

    if (tid < 128) {
        b1L[tid] = b1[tid];
        b2L[tid] = b2[tid];
        int l = block0 + tid;
        ilS[tid] = (l < L) ? i2l[l] : 0;
    }
    for (int idx = tid; idx < 128 * 7; idx += 256)
        wdS[(idx / 7) * 8 + (idx % 7)] = Wd[idx];
    if (tid < 7) bdS[tid] = bd[tid];
    __syncthreads();

    for (int idx = tid; idx < KF * 128; idx += 256) {
        int k = idx >> 7, p = idx & 127;
        int l = block0 + p;
        float v = 0.f;
        if (l < L) {
            int inst = ilS[p];
            if (k < 128)       v = g_locals_feat[(size_t)l * CC + k];
            else if (k < 256)  v = g_globals[(size_t)inst * CC + (k - 128)];
            else if (k < 259)  v = g_centroid[l * 3 + (k - 256)];
            else               v = g_gtlc[inst * 3 + (k - 259)];
        }
        fS[k * 128 + p] = v;
    }
    __syncthreads();

    int h0 = (tid & 15) << 3;
    int p0 = (tid >> 4) << 3;
    float acc[8][8];
    #pragma unroll
    for (int i = 0; i < 8; i++)
        #pragma unroll
        for (int j = 0; j < 8; j++) acc[i][j] = 0.f;

    #pragma unroll 2
    for (int k = 0; k < KF; k++) {
        float4 a0 = *(const float4*)&fS[k * 128 + p0];
        float4 a1 = *(const float4*)&fS[k * 128 + p0 + 4];
        float4 w0 = *(const float4*)&W1[k * 128 + h0];
        float4 w1 = *(const float4*)&W1[k * 128 + h0 + 4];
        float a[8] = {a0.x, a0.y, a0.z, a0.w, a1.x, a1.y, a1.z, a1.w};
        float w[8] = {w0.x, w0.y, w0.z, w0.w, w1.x, w1.y, w1.z, w1.w};
        #pragma unroll
        for (int i = 0; i < 8; i++)
            #pragma unroll
            for (int j = 0; j < 8; j++) acc[i][j] = fmaf(a[i], w[j], acc[i][j]);
    }
    __syncthreads();

    float* hT = fS;
    #pragma unroll
    for (int i = 0; i < 8; i++)
        #pragma unroll
        for (int j = 0; j < 8; j++)
            hT[(h0 + j) * 128 + p0 + i] = fmaxf(acc[i][j] + b1L[h0 + j], 0.f);
    __syncthreads();

    int c0 = h0;
    #pragma unroll
    for (int i = 0; i < 8; i++)
        #pragma unroll
        for (int j = 0; j < 8; j++) acc[i][j] = 0.f;

    #pragma unroll 4
    for (int k = 0; k < 128; k++) {
        float4 a0 = *(const float4*)&hT[k * 128 + p0];
        float4 a1 = *(const float4*)&hT[k * 128 + p0 + 4];
        float4 w0 = *(const float4*)&W2[k * 128 + c0];
        float4 w1 = *(const float4*)&W2[k * 128 + c0 + 4];
        float a[8] = {a0.x, a0.y, a0.z, a0.w, a1.x, a1.y, a1.z, a1.w};
        float w[8] = {w0.x, w0.y, w0.z, w0.w, w1.x, w1.y, w1.z, w1.w};
        #pragma unroll
        for (int i = 0; i < 8; i++)
            #pragma unroll
            for (int j = 0; j < 8; j++) acc[i][j] = fmaf(a[i], w[j], acc[i][j]);
    }

    #pragma unroll
    for (int i = 0; i < 8; i++) {
        int l = block0 + p0 + i;
        #pragma unroll
        for (int j = 0; j < 8; j++) {
            acc[i][j] = fmaxf(acc[i][j] + b2L[c0 + j], 0.f);
            if (l < L) out_fo[(size_t)l * CC + c0 + j] = acc[i][j];
        }
    }
    __syncthreads();

    float* foS = fS;
    #pragma unroll
    for (int i = 0; i < 8; i++)
        #pragma unroll
        for (int j = 0; j < 8; j++)
            foS[(p0 + i) * 133 + c0 + j] = acc[i][j];
    __syncthreads();

    if (tid < 128) {
        int l = block0 + tid;
        if (l < L) {
            float s[7];
            #pragma unroll
            for (int j = 0; j < 7; j++) s[j] = bdS[j];
            for (int c = 0; c < 128; c++) {
                float f = foS[tid * 133 + c];
                #pragma unroll
                for (int j = 0; j < 7; j++) s[j] = fmaf(f, wdS[c * 8 + j], s[j]);
            }
            #pragma unroll
            for (int j = 0; j < 7; j++) out_tf[(size_t)l * 7 + j] = s[j];
        }
    }
}

// ---------------- launch ----------------
extern "C" void kernel_launch(void* const* d_in, const int* in_sizes, int n_in,
                              void* d_out, int out_size) {
    const float* xyz  = (const float*)d_in[0];
    const float* feat = (const float*)d_in[1];
    const float* W1s_ = (const float*)d_in[2];
    const float* b1s_ = (const float*)d_in[3];
    const float* W2s_ = (const float*)d_in[4];
    const float* b2s_ = (const float*)d_in[5];
    const float* W1l  = (const float*)d_in[6];
    const float* b1l  = (const float*)d_in[7];
    const float* W2l  = (const float*)d_in[8];
    const float* b2l  = (const float*)d_in[9];
    const float* Wd   = (const float*)d_in[10];
    const float* bd   = (const float*)d_in[11];
    const int*   l2f  = (const int*)d_in[12];
    const int*   i2l  = (const int*)d_in[13];
    const int*   ils  = (const int*)d_in[14];

    int n = in_sizes[0] / 3;
    int L = in_sizes[13];
    int I = in_sizes[14];

    float* out_tf = (float*)d_out;
    float* out_fo = (float*)d_out + (size_t)L * 7;

    cudaFuncSetAttribute(k_shape, cudaFuncAttributeMaxDynamicSharedMemorySize, SH_SHAPE);
    cudaFuncSetAttribute(k_mlp2,  cudaFuncAttributeMaxDynamicSharedMemorySize, SH_MLP2);

    k_init<<<(L * CC + 255) / 256, 256>>>(L, I);
    k_prep<<<64, 256>>>(W2s_);
    k_count<<<(n + 255) / 256, 256>>>(xyz, l2f, n);
    k_centroid<<<(L + 255) / 256, 256>>>(L);
    k_scan<<<1, 1024>>>(L);
    k_csr<<<(n + 255) / 256, 256>>>(l2f, n);
    k_shape<<<(n + 127) / 128, 256, SH_SHAPE>>>(xyz, W1s_, b1s_, b2s_, n);
    k_featmax<<<(L * 32 + 255) / 256, 256>>>(feat, i2l, L);
    k_gfin<<<(I * CC + 255) / 256, 256>>>(ils, I);
    k_mlp2<<<(L + 127) / 128, 256, SH_MLP2>>>(W1l, b1l, W2l, b2l, Wd, bd, i2l, out_tf, out_fo, L);
}

// round 8
// speedup vs baseline: 1.9361x; 1.1962x over previous
#include <cuda_runtime.h>
#include <cuda_fp16.h>
#include <math_constants.h>
#include <stdint.h>

#define LMAX 100000
#define IMAX 10000
#define NMAX 1000000
#define CC 128

// ---------------- static device scratch ----------------
__device__ int      g_cnt[LMAX];
__device__ float    g_sum[LMAX * 3];
__device__ float    g_centroid[LMAX * 3];
__device__ int      g_off[LMAX + 1];
__device__ int      g_cursor[LMAX];
__device__ int      g_pids[NMAX];
__device__ int      g_plocal[NMAX];
__device__ float    g_shape_max[(size_t)LMAX * CC];
__device__ float    g_locals_feat[(size_t)LMAX * CC];
__device__ int      g_cnt_i[IMAX];
__device__ unsigned g_gkeys[(size_t)IMAX * CC];
__device__ float    g_gtlc[IMAX * 3];
__device__ float    g_globals[(size_t)IMAX * CC];
__device__ __half   g_W2t[128 * 128];     // W2_shape^T fp16: [c][k]
__device__ __half   g_W1lt[128 * 272];    // W1_loc^T fp16, K padded 262->272: [h][k]
__device__ __half   g_W2lt[128 * 128];    // W2_loc^T fp16: [c][k]

// order-preserving float<->uint key for atomicMax on signed floats
__device__ __forceinline__ unsigned fkey(float f) {
    unsigned b = __float_as_uint(f);
    return (b & 0x80000000u) ? ~b : (b | 0x80000000u);
}
__device__ __forceinline__ float funkey(unsigned k) {
    return (k & 0x80000000u) ? __uint_as_float(k & 0x7fffffffu) : __uint_as_float(~k);
}

// ---------------- init ----------------
__global__ void k_init(int L, int I) {
    int idx = blockIdx.x * blockDim.x + threadIdx.x;
    if (idx < L * CC) g_shape_max[idx] = 0.f;
    if (idx < I * CC) g_gkeys[idx] = 0x007fffffu;   // fkey(-inf)
    if (idx < 3 * L) g_sum[idx] = 0.f;
    if (idx < L) { g_cnt[idx] = 0; g_cursor[idx] = 0; }
    if (idx < I) g_cnt_i[idx] = 0;
}

// ---------------- prep: transpose + fp16-convert weights ----------------
__global__ void k_prep(const float* __restrict__ W2) {
    int i = blockIdx.x * blockDim.x + threadIdx.x;
    if (i < 16384) {
        int c = i >> 7, k = i & 127;
        g_W2t[i] = __float2half(W2[k * 128 + c]);
    }
}

__global__ void k_prep2(const float* __restrict__ W1l, const float* __restrict__ W2l) {
    int i = blockIdx.x * blockDim.x + threadIdx.x;
    if (i < 128 * 272) {
        int h = i / 272, k = i - h * 272;
        g_W1lt[i] = (k < 262) ? __float2half(W1l[k * 128 + h]) : __half(0.f);
    }
    if (i < 128 * 128) {
        int c = i >> 7, k = i & 127;
        g_W2lt[i] = __float2half(W2l[k * 128 + c]);
    }
}

// ---------------- centroid count + sum ----------------
__global__ void k_count(const float* __restrict__ xyz, const int* __restrict__ l2f, int n) {
    int i = blockIdx.x * blockDim.x + threadIdx.x;
    if (i >= n) return;
    int l = l2f[i];
    atomicAdd(&g_cnt[l], 1);
    atomicAdd(&g_sum[l * 3 + 0], xyz[i * 3 + 0]);
    atomicAdd(&g_sum[l * 3 + 1], xyz[i * 3 + 1]);
    atomicAdd(&g_sum[l * 3 + 2], xyz[i * 3 + 2]);
}

__global__ void k_centroid(int L) {
    int l = blockIdx.x * blockDim.x + threadIdx.x;
    if (l >= L) return;
    float inv = 1.f / fmaxf((float)g_cnt[l], 1.f);
    g_centroid[l * 3 + 0] = g_sum[l * 3 + 0] * inv;
    g_centroid[l * 3 + 1] = g_sum[l * 3 + 1] * inv;
    g_centroid[l * 3 + 2] = g_sum[l * 3 + 2] * inv;
}

// ---------------- exclusive scan over g_cnt: chunked, one block, warp-shuffle ----------------
__global__ void k_scan(int L) {
    __shared__ int wsum[32];
    int tid = threadIdx.x;                 // 1024 threads
    int chunk = (L + 1023) >> 10;
    int s = tid * chunk;
    int e = s + chunk; if (e > L) e = L;
    if (s > L) s = L;
    int sum = 0;
    for (int i = s; i < e; i++) sum += g_cnt[i];

    int lane = tid & 31, w = tid >> 5;
    int v = sum;
    #pragma unroll
    for (int o = 1; o < 32; o <<= 1) {
        int t = __shfl_up_sync(0xffffffffu, v, o);
        if (lane >= o) v += t;
    }
    if (lane == 31) wsum[w] = v;
    __syncthreads();
    if (w == 0) {
        int x = wsum[lane];
        #pragma unroll
        for (int o = 1; o < 32; o <<= 1) {
            int t = __shfl_up_sync(0xffffffffu, x, o);
            if (lane >= o) x += t;
        }
        wsum[lane] = x;
    }
    __syncthreads();
    int excl = v - sum + (w > 0 ? wsum[w - 1] : 0);
    int run = excl;
    for (int i = s; i < e; i++) { int c = g_cnt[i]; g_off[i] = run; run += c; }
    if (tid == 1023) g_off[L] = run;
}

// ---------------- CSR scatter ----------------
__global__ void k_csr(const int* __restrict__ l2f, int n) {
    int i = blockIdx.x * blockDim.x + threadIdx.x;
    if (i >= n) return;
    int l = l2f[i];
    int pos = atomicAdd(&g_cursor[l], 1);
    int slot = g_off[l] + pos;
    g_pids[slot] = i;
    g_plocal[slot] = l;
}

// ---------------- mma helper ----------------
__device__ __forceinline__ void mma16816(float* d, const unsigned* a, unsigned b0, unsigned b1) {
    asm volatile(
        "mma.sync.aligned.m16n8k16.row.col.f32.f16.f16.f32 "
        "{%0,%1,%2,%3}, {%4,%5,%6,%7}, {%8,%9}, {%0,%1,%2,%3};"
        : "+f"(d[0]), "+f"(d[1]), "+f"(d[2]), "+f"(d[3])
        : "r"(a[0]), "r"(a[1]), "r"(a[2]), "r"(a[3]), "r"(b0), "r"(b1));
}

// ---------------- shape MLP: layer1 fp32 -> fp16, layer2 on tensor cores ----------------
#define STRH 136
#define SH_SHAPE (128 * STRH * 2 * 2 + (384 + 128 + 128) * 4 + 128 * 4)

__global__ __launch_bounds__(256) void k_shape(
    const float* __restrict__ xyz,
    const float* __restrict__ W1, const float* __restrict__ b1,
    const float* __restrict__ b2, int n)
{
    extern __shared__ char smraw[];
    __half* hA  = (__half*)smraw;                        // [128][STRH]
    __half* W2t = (__half*)(smraw + 128 * STRH * 2);     // [128][STRH]
    float*  outS = (float*)smraw;                        // reuse, [128][128]
    float*  ext = (float*)(smraw + 128 * STRH * 2 * 2);
    float*  W1s = ext;          // [dim][k]
    float*  b1s = ext + 384;
    float*  b2s = ext + 512;
    int*   lidS = (int*)(ext + 640);

    int tid = threadIdx.x;
    int tile0 = blockIdx.x * 128;

    for (int i = tid; i < 384; i += 256) W1s[i] = W1[i];
    if (tid < 128) { b1s[tid] = b1[tid]; b2s[tid] = b2[tid]; }
    __syncthreads();

    // layer1 (fp32 math, fp16 store) + W2t smem copy
    {
        int p = tid & 127, hid = tid >> 7;
        int row = tile0 + p;
        float cx = 0.f, cy = 0.f, cz = 0.f;
        int l = -1;
        bool valid = (row < n);
        if (valid) {
            int pid = g_pids[row];
            l = g_plocal[row];
            cx = xyz[pid * 3 + 0] - g_centroid[l * 3 + 0];
            cy = xyz[pid * 3 + 1] - g_centroid[l * 3 + 1];
            cz = xyz[pid * 3 + 2] - g_centroid[l * 3 + 2];
        }
        if (hid == 0) lidS[p] = l;
        int k0 = hid * 64;
        #pragma unroll 8
        for (int k = k0; k < k0 + 64; k += 2) {
            float h0 = fmaf(cx, W1s[k],   fmaf(cy, W1s[128 + k],   fmaf(cz, W1s[256 + k],   b1s[k])));
            float h1 = fmaf(cx, W1s[k+1], fmaf(cy, W1s[128 + k+1], fmaf(cz, W1s[256 + k+1], b1s[k+1])));
            h0 = valid ? fmaxf(h0, 0.f) : 0.f;
            h1 = valid ? fmaxf(h1, 0.f) : 0.f;
            *(__half2*)&hA[p * STRH + k] = __floats2half2_rn(h0, h1);
        }
        const unsigned* src = (const unsigned*)g_W2t;
        for (int i = tid; i < 8192; i += 256) {
            int c = i >> 6, k2 = (i & 63) << 1;
            *(unsigned*)&W2t[c * STRH + k2] = src[i];
        }
    }
    __syncthreads();

    // tensor-core GEMM: 128x128x128, warps 4(m) x 2(n)
    int wid = tid >> 5, lane = tid & 31;
    int m0 = (wid >> 1) * 32, n0 = (wid & 1) * 64;
    int g = lane >> 2, t4 = (lane & 3) * 2;

    float acc[2][8][4];
    #pragma unroll
    for (int a = 0; a < 2; a++)
        #pragma unroll
        for (int b_ = 0; b_ < 8; b_++)
            #pragma unroll
            for (int c = 0; c < 4; c++) acc[a][b_][c] = 0.f;

    #pragma unroll
    for (int kk = 0; kk < 128; kk += 16) {
        unsigned afr[2][4];
        #pragma unroll
        for (int mt = 0; mt < 2; mt++) {
            const __half* base = &hA[(m0 + mt * 16 + g) * STRH + kk + t4];
            afr[mt][0] = *(const unsigned*)base;
            afr[mt][1] = *(const unsigned*)(base + 8 * STRH);
            afr[mt][2] = *(const unsigned*)(base + 8);
            afr[mt][3] = *(const unsigned*)(base + 8 * STRH + 8);
        }
        #pragma unroll
        for (int nt = 0; nt < 8; nt++) {
            const __half* bb = &W2t[(n0 + nt * 8 + g) * STRH + kk + t4];
            unsigned b0 = *(const unsigned*)bb;
            unsigned b1v = *(const unsigned*)(bb + 8);
            mma16816(acc[0][nt], afr[0], b0, b1v);
            mma16816(acc[1][nt], afr[1], b0, b1v);
        }
    }
    __syncthreads();   // done reading hA/W2t -> reuse as outS

    #pragma unroll
    for (int mt = 0; mt < 2; mt++) {
        #pragma unroll
        for (int nt = 0; nt < 8; nt++) {
            int r0 = m0 + mt * 16 + g;
            int c = n0 + nt * 8 + t4;
            float2 v0, v1;
            v0.x = fmaxf(acc[mt][nt][0] + b2s[c], 0.f);
            v0.y = fmaxf(acc[mt][nt][1] + b2s[c + 1], 0.f);
            v1.x = fmaxf(acc[mt][nt][2] + b2s[c], 0.f);
            v1.y = fmaxf(acc[mt][nt][3] + b2s[c + 1], 0.f);
            *(float2*)&outS[r0 * 128 + c] = v0;
            *(float2*)&outS[(r0 + 8) * 128 + c] = v1;
        }
    }
    __syncthreads();

    // segmented max over sorted locals
    if (tid < 128) {
        int c = tid;
        int cur = -2, s = 0;
        float m = 0.f;
        for (int r = 0; r < 128; r++) {
            int l = lidS[r];
            float v = outS[r * 128 + c];
            if (l != cur) {
                if (cur >= 0) {
                    float* dst = &g_shape_max[(size_t)cur * CC + c];
                    if (s > 0) *dst = m;
                    else atomicMax((int*)dst, __float_as_int(m));
                }
                cur = l; m = v; s = r;
            } else m = fmaxf(m, v);
        }
        if (cur >= 0)
            atomicMax((int*)&g_shape_max[(size_t)cur * CC + c], __float_as_int(m));
    }
}

// ---------------- fg_feat segmax + locals_feat + global key-max ----------------
__global__ void k_featmax(const float* __restrict__ feat, const int* __restrict__ i2l, int L) {
    int gt = blockIdx.x * blockDim.x + threadIdx.x;
    int w = gt >> 5, lane = gt & 31;
    if (w >= L) return;
    int s = g_off[w], e = g_off[w + 1];
    float m0 = -CUDART_INF_F, m1 = m0, m2 = m0, m3 = m0;
    for (int p = s; p < e; p++) {
        const float* row = feat + (size_t)g_pids[p] * CC;
        m0 = fmaxf(m0, row[lane]);
        m1 = fmaxf(m1, row[lane + 32]);
        m2 = fmaxf(m2, row[lane + 64]);
        m3 = fmaxf(m3, row[lane + 96]);
    }
    if (e <= s) { m0 = m1 = m2 = m3 = 0.f; }
    size_t base = (size_t)w * CC;
    float v0 = m0 + g_shape_max[base + lane];
    float v1 = m1 + g_shape_max[base + lane + 32];
    float v2 = m2 + g_shape_max[base + lane + 64];
    float v3 = m3 + g_shape_max[base + lane + 96];
    g_locals_feat[base + lane]      = v0;
    g_locals_feat[base + lane + 32] = v1;
    g_locals_feat[base + lane + 64] = v2;
    g_locals_feat[base + lane + 96] = v3;
    int inst = i2l[w];
    size_t gb = (size_t)inst * CC;
    atomicMax(&g_gkeys[gb + lane],      fkey(v0));
    atomicMax(&g_gkeys[gb + lane + 32], fkey(v1));
    atomicMax(&g_gkeys[gb + lane + 64], fkey(v2));
    atomicMax(&g_gkeys[gb + lane + 96], fkey(v3));
    if (lane == 0) atomicAdd(&g_cnt_i[inst], 1);
}

// ---------------- finalize globals + target centers ----------------
__global__ void k_gfin(const int* __restrict__ ils, int I) {
    int idx = blockIdx.x * blockDim.x + threadIdx.x;
    if (idx < I * CC) {
        int i = idx >> 7;
        g_globals[idx] = (g_cnt_i[i] > 0) ? funkey(g_gkeys[idx]) : 0.f;
    }
    if (idx < I * 3) {
        int i = idx / 3, d = idx % 3;
        g_gtlc[idx] = g_centroid[ils[i] * 3 + d];
    }
}

// ---------------- locals MLP on tensor cores (262->128 relu ->128 relu) + decoder ----------------
// smem: A1 half[128][280] | B1 half[128][280] | ext: b1L,b2L,wdS(1024),bdS(8),ilS(128i)
// phase2 reuses A1 as hA2 half[128][136], B1 as W2s half[128][136]; phase3 reuses A1 as foS f32[128][133]
#define KF 262
#define KP 272
#define STRL 280
#define SH_MLP2 (2 * 128 * STRL * 2 + (128 + 128 + 1024 + 8) * 4 + 128 * 4)

__global__ __launch_bounds__(256) void k_mlp2(
    const float* __restrict__ b1, const float* __restrict__ b2,
    const float* __restrict__ Wd, const float* __restrict__ bd,
    const int* __restrict__ i2l,
    float* __restrict__ out_tf, float* __restrict__ out_fo, int L)
{
    extern __shared__ char smraw[];
    __half* A1 = (__half*)smraw;                         // [128][STRL]
    __half* B1 = (__half*)(smraw + 128 * STRL * 2);      // [128][STRL]
    float*  ext = (float*)(smraw + 2 * 128 * STRL * 2);
    float* b1L = ext;           // 128
    float* b2L = ext + 128;     // 128
    float* wdS = ext + 256;     // [c][8]
    float* bdS = ext + 1280;    // 8
    int*   ilS = (int*)(ext + 1288);
    __half* hA2 = (__half*)smraw;                        // [128][136] (phase 2)
    __half* W2s = (__half*)(smraw + 128 * STRL * 2);     // [128][136] (phase 2)
    float*  foS = (float*)smraw;                         // [128][133] (phase 3)

    int tid = threadIdx.x;
    int block0 = blockIdx.x * 128;

    if (tid < 128) {
        b1L[tid] = b1[tid];
        b2L[tid] = b2[tid];
        int l = block0 + tid;
        ilS[tid] = (l < L) ? i2l[l] : 0;
    }
    for (int idx = tid; idx < 128 * 7; idx += 256)
        wdS[(idx / 7) * 8 + (idx % 7)] = Wd[idx];
    if (tid < 7) bdS[tid] = bd[tid];
    __syncthreads();

    // assemble feat fp16 into A1[p][k], copy W1lt into B1[h][k]
    for (int idx = tid; idx < 128 * KP; idx += 256) {
        int p = idx / KP, k = idx - p * KP;
        int l = block0 + p;
        float v = 0.f;
        if (l < L && k < KF) {
            int inst = ilS[p];
            if (k < 128)       v = g_locals_feat[(size_t)l * CC + k];
            else if (k < 256)  v = g_globals[(size_t)inst * CC + (k - 128)];
            else if (k < 259)  v = g_centroid[l * 3 + (k - 256)];
            else               v = g_gtlc[inst * 3 + (k - 259)];
        }
        A1[p * STRL + k] = __float2half(v);
    }
    {
        const unsigned* src = (const unsigned*)g_W1lt;   // [h][272] as pairs
        for (int i = tid; i < 128 * (KP / 2); i += 256) {
            int h = i / (KP / 2), k2 = (i - h * (KP / 2)) << 1;
            *(unsigned*)&B1[h * STRL + k2] = src[i];
        }
    }
    __syncthreads();

    int wid = tid >> 5, lane = tid & 31;
    int m0 = (wid >> 1) * 32, n0 = (wid & 1) * 64;
    int g = lane >> 2, t4 = (lane & 3) * 2;

    float acc[2][8][4];
    #pragma unroll
    for (int a = 0; a < 2; a++)
        #pragma unroll
        for (int b_ = 0; b_ < 8; b_++)
            #pragma unroll
            for (int c = 0; c < 4; c++) acc[a][b_][c] = 0.f;

    // GEMM1: [128 x 128] = A1[128 x 272] * W1lt^T, K=272
    #pragma unroll
    for (int kk = 0; kk < KP; kk += 16) {
        unsigned afr[2][4];
        #pragma unroll
        for (int mt = 0; mt < 2; mt++) {
            const __half* base = &A1[(m0 + mt * 16 + g) * STRL + kk + t4];
            afr[mt][0] = *(const unsigned*)base;
            afr[mt][1] = *(const unsigned*)(base + 8 * STRL);
            afr[mt][2] = *(const unsigned*)(base + 8);
            afr[mt][3] = *(const unsigned*)(base + 8 * STRL + 8);
        }
        #pragma unroll
        for (int nt = 0; nt < 8; nt++) {
            const __half* bb = &B1[(n0 + nt * 8 + g) * STRL + kk + t4];
            unsigned b0 = *(const unsigned*)bb;
            unsigned b1v = *(const unsigned*)(bb + 8);
            mma16816(acc[0][nt], afr[0], b0, b1v);
            mma16816(acc[1][nt], afr[1], b0, b1v);
        }
    }
    __syncthreads();  // A1/B1 reads done -> reuse regions

    // epilogue 1: relu(acc + b1) -> hA2[p][h] fp16; copy W2lt into W2s
    #pragma unroll
    for (int mt = 0; mt < 2; mt++) {
        #pragma unroll
        for (int nt = 0; nt < 8; nt++) {
            int r0 = m0 + mt * 16 + g;
            int c = n0 + nt * 8 + t4;
            float h00 = fmaxf(acc[mt][nt][0] + b1L[c], 0.f);
            float h01 = fmaxf(acc[mt][nt][1] + b1L[c + 1], 0.f);
            float h10 = fmaxf(acc[mt][nt][2] + b1L[c], 0.f);
            float h11 = fmaxf(acc[mt][nt][3] + b1L[c + 1], 0.f);
            *(__half2*)&hA2[r0 * STRH + c] = __floats2half2_rn(h00, h01);
            *(__half2*)&hA2[(r0 + 8) * STRH + c] = __floats2half2_rn(h10, h11);
        }
    }
    {
        const unsigned* src = (const unsigned*)g_W2lt;
        for (int i = tid; i < 8192; i += 256) {
            int c = i >> 6, k2 = (i & 63) << 1;
            *(unsigned*)&W2s[c * STRH + k2] = src[i];
        }
    }
    __syncthreads();

    // GEMM2: [128 x 128] = hA2[128 x 128] * W2lt^T, K=128
    #pragma unroll
    for (int a = 0; a < 2; a++)
        #pragma unroll
        for (int b_ = 0; b_ < 8; b_++)
            #pragma unroll
            for (int c = 0; c < 4; c++) acc[a][b_][c] = 0.f;

    #pragma unroll
    for (int kk = 0; kk < 128; kk += 16) {
        unsigned afr[2][4];
        #pragma unroll
        for (int mt = 0; mt < 2; mt++) {
            const __half* base = &hA2[(m0 + mt * 16 + g) * STRH + kk + t4];
            afr[mt][0] = *(const unsigned*)base;
            afr[mt][1] = *(const unsigned*)(base + 8 * STRH);
            afr[mt][2] = *(const unsigned*)(base + 8);
            afr[mt][3] = *(const unsigned*)(base + 8 * STRH + 8);
        }
        #pragma unroll
        for (int nt = 0; nt < 8; nt++) {
            const __half* bb = &W2s[(n0 + nt * 8 + g) * STRH + kk + t4];
            unsigned b0 = *(const unsigned*)bb;
            unsigned b1v = *(const unsigned*)(bb + 8);
            mma16816(acc[0][nt], afr[0], b0, b1v);
            mma16816(acc[1][nt], afr[1], b0, b1v);
        }
    }
    __syncthreads();  // hA2/W2s reads done -> reuse as foS

    // epilogue 2: relu(acc + b2) -> out_fo (global) + foS (smem, f32)
    #pragma unroll
    for (int mt = 0; mt < 2; mt++) {
        #pragma unroll
        for (int nt = 0; nt < 8; nt++) {
            int r0 = m0 + mt * 16 + g;
            int c = n0 + nt * 8 + t4;
            float v00 = fmaxf(acc[mt][nt][0] + b2L[c], 0.f);
            float v01 = fmaxf(acc[mt][nt][1] + b2L[c + 1], 0.f);
            float v10 = fmaxf(acc[mt][nt][2] + b2L[c], 0.f);
            float v11 = fmaxf(acc[mt][nt][3] + b2L[c + 1], 0.f);
            foS[r0 * 133 + c] = v00; foS[r0 * 133 + c + 1] = v01;
            foS[(r0 + 8) * 133 + c] = v10; foS[(r0 + 8) * 133 + c + 1] = v11;
            int l0 = block0 + r0, l1 = block0 + r0 + 8;
            if (l0 < L) { float2 s; s.x = v00; s.y = v01; *(float2*)&out_fo[(size_t)l0 * CC + c] = s; }
            if (l1 < L) { float2 s; s.x = v10; s.y = v11; *(float2*)&out_fo[(size_t)l1 * CC + c] = s; }
        }
    }
    __syncthreads();

    // decoder: 128 threads, one local each, 7 outputs
    if (tid < 128) {
        int l = block0 + tid;
        if (l < L) {
            float s[7];
            #pragma unroll
            for (int j = 0; j < 7; j++) s[j] = bdS[j];
            for (int c = 0; c < 128; c++) {
                float f = foS[tid * 133 + c];
                #pragma unroll
                for (int j = 0; j < 7; j++) s[j] = fmaf(f, wdS[c * 8 + j], s[j]);
            }
            #pragma unroll
            for (int j = 0; j < 7; j++) out_tf[(size_t)l * 7 + j] = s[j];
        }
    }
}

// ---------------- launch ----------------
extern "C" void kernel_launch(void* const* d_in, const int* in_sizes, int n_in,
                              void* d_out, int out_size) {
    const float* xyz  = (const float*)d_in[0];
    const float* feat = (const float*)d_in[1];
    const float* W1s_ = (const float*)d_in[2];
    const float* b1s_ = (const float*)d_in[3];
    const float* W2s_ = (const float*)d_in[4];
    const float* b2s_ = (const float*)d_in[5];
    const float* W1l  = (const float*)d_in[6];
    const float* b1l  = (const float*)d_in[7];
    const float* W2l  = (const float*)d_in[8];
    const float* b2l  = (const float*)d_in[9];
    const float* Wd   = (const float*)d_in[10];
    const float* bd   = (const float*)d_in[11];
    const int*   l2f  = (const int*)d_in[12];
    const int*   i2l  = (const int*)d_in[13];
    const int*   ils  = (const int*)d_in[14];

    int n = in_sizes[0] / 3;
    int L = in_sizes[13];
    int I = in_sizes[14];

    float* out_tf = (float*)d_out;
    float* out_fo = (float*)d_out + (size_t)L * 7;

    cudaFuncSetAttribute(k_shape, cudaFuncAttributeMaxDynamicSharedMemorySize, SH_SHAPE);
    cudaFuncSetAttribute(k_mlp2,  cudaFuncAttributeMaxDynamicSharedMemorySize, SH_MLP2);

    k_init<<<(L * CC + 255) / 256, 256>>>(L, I);
    k_prep<<<64, 256>>>(W2s_);
    k_prep2<<<(128 * 272 + 255) / 256, 256>>>(W1l, W2l);
    k_count<<<(n + 255) / 256, 256>>>(xyz, l2f, n);
    k_centroid<<<(L + 255) / 256, 256>>>(L);
    k_scan<<<1, 1024>>>(L);
    k_csr<<<(n + 255) / 256, 256>>>(l2f, n);
    k_shape<<<(n + 127) / 128, 256, SH_SHAPE>>>(xyz, W1s_, b1s_, b2s_, n);
    k_featmax<<<(L * 32 + 255) / 256, 256>>>(feat, i2l, L);
    k_gfin<<<(I * CC + 255) / 256, 256>>>(ils, I);
    k_mlp2<<<(L + 127) / 128, 256, SH_MLP2>>>(b1l, b2l, Wd, bd, i2l, out_tf, out_fo, L);
}

// round 9
// speedup vs baseline: 1.9470x; 1.0057x over previous
#include <cuda_runtime.h>
#include <cuda_fp16.h>
#include <math_constants.h>
#include <stdint.h>

#define LMAX 100000
#define IMAX 10000
#define NMAX 1000000
#define CC 128

// ---------------- static device scratch ----------------
__device__ int      g_cnt[LMAX];
__device__ float    g_sum[LMAX * 3];
__device__ float    g_centroid[LMAX * 3];
__device__ int      g_off[LMAX + 1];
__device__ int      g_cursor[LMAX];
__device__ int      g_pids[NMAX];
__device__ int      g_plocal[NMAX];
__device__ float    g_shape_max[(size_t)LMAX * CC];
__device__ float    g_locals_feat[(size_t)LMAX * CC];
__device__ int      g_cnt_i[IMAX];
__device__ unsigned g_gkeys[(size_t)IMAX * CC];
__device__ float    g_gtlc[IMAX * 3];
__device__ float    g_globals[(size_t)IMAX * CC];
__device__ __half   g_W2t[128 * 128];     // W2_shape^T fp16: [c][k]
__device__ __half   g_W1lt[128 * 272];    // W1_loc^T fp16, K padded 262->272: [h][k]
__device__ __half   g_W2lt[128 * 128];    // W2_loc^T fp16: [c][k]

// order-preserving float<->uint key for atomicMax on signed floats
__device__ __forceinline__ unsigned fkey(float f) {
    unsigned b = __float_as_uint(f);
    return (b & 0x80000000u) ? ~b : (b | 0x80000000u);
}
__device__ __forceinline__ float funkey(unsigned k) {
    return (k & 0x80000000u) ? __uint_as_float(k & 0x7fffffffu) : __uint_as_float(~k);
}

// ---------------- init ----------------
__global__ void k_init(int L, int I) {
    int idx = blockIdx.x * blockDim.x + threadIdx.x;
    if (idx < L * CC) g_shape_max[idx] = 0.f;
    if (idx < I * CC) g_gkeys[idx] = 0x007fffffu;   // fkey(-inf)
    if (idx < 3 * L) g_sum[idx] = 0.f;
    if (idx < L) { g_cnt[idx] = 0; g_cursor[idx] = 0; }
    if (idx < I) g_cnt_i[idx] = 0;
}

// ---------------- prep: transpose + fp16-convert weights ----------------
__global__ void k_prep(const float* __restrict__ W2) {
    int i = blockIdx.x * blockDim.x + threadIdx.x;
    if (i < 16384) {
        int c = i >> 7, k = i & 127;
        g_W2t[i] = __float2half(W2[k * 128 + c]);
    }
}

__global__ void k_prep2(const float* __restrict__ W1l, const float* __restrict__ W2l) {
    int i = blockIdx.x * blockDim.x + threadIdx.x;
    if (i < 128 * 272) {
        int h = i / 272, k = i - h * 272;
        g_W1lt[i] = (k < 262) ? __float2half(W1l[k * 128 + h]) : __half(0.f);
    }
    if (i < 128 * 128) {
        int c = i >> 7, k = i & 127;
        g_W2lt[i] = __float2half(W2l[k * 128 + c]);
    }
}

// ---------------- centroid count + sum ----------------
__global__ void k_count(const float* __restrict__ xyz, const int* __restrict__ l2f, int n) {
    int i = blockIdx.x * blockDim.x + threadIdx.x;
    if (i >= n) return;
    int l = l2f[i];
    atomicAdd(&g_cnt[l], 1);
    atomicAdd(&g_sum[l * 3 + 0], xyz[i * 3 + 0]);
    atomicAdd(&g_sum[l * 3 + 1], xyz[i * 3 + 1]);
    atomicAdd(&g_sum[l * 3 + 2], xyz[i * 3 + 2]);
}

__global__ void k_centroid(int L) {
    int l = blockIdx.x * blockDim.x + threadIdx.x;
    if (l >= L) return;
    float inv = 1.f / fmaxf((float)g_cnt[l], 1.f);
    g_centroid[l * 3 + 0] = g_sum[l * 3 + 0] * inv;
    g_centroid[l * 3 + 1] = g_sum[l * 3 + 1] * inv;
    g_centroid[l * 3 + 2] = g_sum[l * 3 + 2] * inv;
}

// ---------------- exclusive scan over g_cnt: chunked, one block, warp-shuffle ----------------
__global__ void k_scan(int L) {
    __shared__ int wsum[32];
    int tid = threadIdx.x;                 // 1024 threads
    int chunk = (L + 1023) >> 10;
    int s = tid * chunk;
    int e = s + chunk; if (e > L) e = L;
    if (s > L) s = L;
    int sum = 0;
    for (int i = s; i < e; i++) sum += g_cnt[i];

    int lane = tid & 31, w = tid >> 5;
    int v = sum;
    #pragma unroll
    for (int o = 1; o < 32; o <<= 1) {
        int t = __shfl_up_sync(0xffffffffu, v, o);
        if (lane >= o) v += t;
    }
    if (lane == 31) wsum[w] = v;
    __syncthreads();
    if (w == 0) {
        int x = wsum[lane];
        #pragma unroll
        for (int o = 1; o < 32; o <<= 1) {
            int t = __shfl_up_sync(0xffffffffu, x, o);
            if (lane >= o) x += t;
        }
        wsum[lane] = x;
    }
    __syncthreads();
    int excl = v - sum + (w > 0 ? wsum[w - 1] : 0);
    int run = excl;
    for (int i = s; i < e; i++) { int c = g_cnt[i]; g_off[i] = run; run += c; }
    if (tid == 1023) g_off[L] = run;
}

// ---------------- CSR scatter ----------------
__global__ void k_csr(const int* __restrict__ l2f, int n) {
    int i = blockIdx.x * blockDim.x + threadIdx.x;
    if (i >= n) return;
    int l = l2f[i];
    int pos = atomicAdd(&g_cursor[l], 1);
    int slot = g_off[l] + pos;
    g_pids[slot] = i;
    g_plocal[slot] = l;
}

// ---------------- mma / ldmatrix helpers ----------------
__device__ __forceinline__ void mma16816(float* d, const unsigned* a, unsigned b0, unsigned b1) {
    asm volatile(
        "mma.sync.aligned.m16n8k16.row.col.f32.f16.f16.f32 "
        "{%0,%1,%2,%3}, {%4,%5,%6,%7}, {%8,%9}, {%0,%1,%2,%3};"
        : "+f"(d[0]), "+f"(d[1]), "+f"(d[2]), "+f"(d[3])
        : "r"(a[0]), "r"(a[1]), "r"(a[2]), "r"(a[3]), "r"(b0), "r"(b1));
}

__device__ __forceinline__ void ldm_x4(unsigned* r, uint32_t saddr) {
    asm volatile(
        "ldmatrix.sync.aligned.m8n8.x4.shared.b16 {%0,%1,%2,%3}, [%4];"
        : "=r"(r[0]), "=r"(r[1]), "=r"(r[2]), "=r"(r[3]) : "r"(saddr));
}

// A-matrix ldmatrix lane address offset (in halves) for a 16x16 tile at (row0, k0):
//   lanes 0-15 -> rows row0+lane,   col k0
//   lanes 16-31 -> rows row0+lane-16, col k0+8
// -> regs r0..r3 = a0..a3 of mma m16n8k16.
// B-matrix: one x4 covers two n8 tiles:
//   lanes 0-7:  n0+lane,    k0    ; lanes 8-15: n0+lane-8,  k0+8
//   lanes 16-23: n0+8+..,   k0    ; lanes 24-31: n0+8+..,   k0+8
// -> r0,r1 = b0,b1 of tile n0; r2,r3 = b0,b1 of tile n0+8.

// ---------------- shape MLP: layer1 fp32 -> fp16, layer2 on tensor cores ----------------
#define STRH 136
#define SH_SHAPE (128 * STRH * 2 * 2 + (384 + 128 + 128) * 4 + 128 * 4)

__global__ __launch_bounds__(256) void k_shape(
    const float* __restrict__ xyz,
    const float* __restrict__ W1, const float* __restrict__ b1,
    const float* __restrict__ b2, int n)
{
    extern __shared__ char smraw[];
    __half* hA  = (__half*)smraw;                        // [128][STRH]
    __half* W2t = (__half*)(smraw + 128 * STRH * 2);     // [128][STRH]
    float*  outS = (float*)smraw;                        // reuse, [128][128]
    float*  ext = (float*)(smraw + 128 * STRH * 2 * 2);
    float*  W1s = ext;          // [dim][k]
    float*  b1s = ext + 384;
    float*  b2s = ext + 512;
    int*   lidS = (int*)(ext + 640);

    int tid = threadIdx.x;
    int tile0 = blockIdx.x * 128;

    for (int i = tid; i < 384; i += 256) W1s[i] = W1[i];
    if (tid < 128) { b1s[tid] = b1[tid]; b2s[tid] = b2[tid]; }
    __syncthreads();

    // layer1 (fp32 math, fp16 store) + W2t smem copy
    {
        int p = tid & 127, hid = tid >> 7;
        int row = tile0 + p;
        float cx = 0.f, cy = 0.f, cz = 0.f;
        int l = -1;
        bool valid = (row < n);
        if (valid) {
            int pid = g_pids[row];
            l = g_plocal[row];
            cx = xyz[pid * 3 + 0] - g_centroid[l * 3 + 0];
            cy = xyz[pid * 3 + 1] - g_centroid[l * 3 + 1];
            cz = xyz[pid * 3 + 2] - g_centroid[l * 3 + 2];
        }
        if (hid == 0) lidS[p] = l;
        int k0 = hid * 64;
        #pragma unroll 8
        for (int k = k0; k < k0 + 64; k += 2) {
            float h0 = fmaf(cx, W1s[k],   fmaf(cy, W1s[128 + k],   fmaf(cz, W1s[256 + k],   b1s[k])));
            float h1 = fmaf(cx, W1s[k+1], fmaf(cy, W1s[128 + k+1], fmaf(cz, W1s[256 + k+1], b1s[k+1])));
            h0 = valid ? fmaxf(h0, 0.f) : 0.f;
            h1 = valid ? fmaxf(h1, 0.f) : 0.f;
            *(__half2*)&hA[p * STRH + k] = __floats2half2_rn(h0, h1);
        }
        const unsigned* src = (const unsigned*)g_W2t;
        for (int i = tid; i < 8192; i += 256) {
            int c = i >> 6, k2 = (i & 63) << 1;
            *(unsigned*)&W2t[c * STRH + k2] = src[i];
        }
    }
    __syncthreads();

    // tensor-core GEMM: 128x128x128, warps 4(m) x 2(n), ldmatrix fragment loads
    int wid = tid >> 5, lane = tid & 31;
    int m0 = (wid >> 1) * 32, n0 = (wid & 1) * 64;
    int g = lane >> 2, t4 = (lane & 3) * 2;

    uint32_t hA_s  = (uint32_t)__cvta_generic_to_shared(hA);
    uint32_t W2t_s = (uint32_t)__cvta_generic_to_shared(W2t);
    uint32_t aAddr = hA_s  + ((m0 + (lane & 15)) * STRH + ((lane >> 4) << 3)) * 2;
    uint32_t bAddr = W2t_s + ((n0 + ((lane >> 4) << 3) + (lane & 7)) * STRH + (((lane >> 3) & 1) << 3)) * 2;

    float acc[2][8][4];
    #pragma unroll
    for (int a = 0; a < 2; a++)
        #pragma unroll
        for (int b_ = 0; b_ < 8; b_++)
            #pragma unroll
            for (int c = 0; c < 4; c++) acc[a][b_][c] = 0.f;

    #pragma unroll
    for (int kk = 0; kk < 128; kk += 16) {
        unsigned af[2][4];
        ldm_x4(af[0], aAddr + kk * 2);
        ldm_x4(af[1], aAddr + kk * 2 + 16 * STRH * 2);
        #pragma unroll
        for (int np = 0; np < 4; np++) {
            unsigned bf[4];
            ldm_x4(bf, bAddr + kk * 2 + np * 16 * STRH * 2);
            mma16816(acc[0][2*np],   af[0], bf[0], bf[1]);
            mma16816(acc[1][2*np],   af[1], bf[0], bf[1]);
            mma16816(acc[0][2*np+1], af[0], bf[2], bf[3]);
            mma16816(acc[1][2*np+1], af[1], bf[2], bf[3]);
        }
    }
    __syncthreads();   // done reading hA/W2t -> reuse as outS

    #pragma unroll
    for (int mt = 0; mt < 2; mt++) {
        #pragma unroll
        for (int nt = 0; nt < 8; nt++) {
            int r0 = m0 + mt * 16 + g;
            int c = n0 + nt * 8 + t4;
            float2 v0, v1;
            v0.x = fmaxf(acc[mt][nt][0] + b2s[c], 0.f);
            v0.y = fmaxf(acc[mt][nt][1] + b2s[c + 1], 0.f);
            v1.x = fmaxf(acc[mt][nt][2] + b2s[c], 0.f);
            v1.y = fmaxf(acc[mt][nt][3] + b2s[c + 1], 0.f);
            *(float2*)&outS[r0 * 128 + c] = v0;
            *(float2*)&outS[(r0 + 8) * 128 + c] = v1;
        }
    }
    __syncthreads();

    // segmented max over sorted locals
    if (tid < 128) {
        int c = tid;
        int cur = -2, s = 0;
        float m = 0.f;
        for (int r = 0; r < 128; r++) {
            int l = lidS[r];
            float v = outS[r * 128 + c];
            if (l != cur) {
                if (cur >= 0) {
                    float* dst = &g_shape_max[(size_t)cur * CC + c];
                    if (s > 0) *dst = m;
                    else atomicMax((int*)dst, __float_as_int(m));
                }
                cur = l; m = v; s = r;
            } else m = fmaxf(m, v);
        }
        if (cur >= 0)
            atomicMax((int*)&g_shape_max[(size_t)cur * CC + c], __float_as_int(m));
    }
}

// ---------------- fg_feat segmax + locals_feat + global key-max ----------------
__global__ void k_featmax(const float* __restrict__ feat, const int* __restrict__ i2l, int L) {
    int gt = blockIdx.x * blockDim.x + threadIdx.x;
    int w = gt >> 5, lane = gt & 31;
    if (w >= L) return;
    int s = g_off[w], e = g_off[w + 1];
    float m0 = -CUDART_INF_F, m1 = m0, m2 = m0, m3 = m0;
    for (int p = s; p < e; p++) {
        const float* row = feat + (size_t)g_pids[p] * CC;
        m0 = fmaxf(m0, row[lane]);
        m1 = fmaxf(m1, row[lane + 32]);
        m2 = fmaxf(m2, row[lane + 64]);
        m3 = fmaxf(m3, row[lane + 96]);
    }
    if (e <= s) { m0 = m1 = m2 = m3 = 0.f; }
    size_t base = (size_t)w * CC;
    float v0 = m0 + g_shape_max[base + lane];
    float v1 = m1 + g_shape_max[base + lane + 32];
    float v2 = m2 + g_shape_max[base + lane + 64];
    float v3 = m3 + g_shape_max[base + lane + 96];
    g_locals_feat[base + lane]      = v0;
    g_locals_feat[base + lane + 32] = v1;
    g_locals_feat[base + lane + 64] = v2;
    g_locals_feat[base + lane + 96] = v3;
    int inst = i2l[w];
    size_t gb = (size_t)inst * CC;
    atomicMax(&g_gkeys[gb + lane],      fkey(v0));
    atomicMax(&g_gkeys[gb + lane + 32], fkey(v1));
    atomicMax(&g_gkeys[gb + lane + 64], fkey(v2));
    atomicMax(&g_gkeys[gb + lane + 96], fkey(v3));
    if (lane == 0) atomicAdd(&g_cnt_i[inst], 1);
}

// ---------------- finalize globals + target centers ----------------
__global__ void k_gfin(const int* __restrict__ ils, int I) {
    int idx = blockIdx.x * blockDim.x + threadIdx.x;
    if (idx < I * CC) {
        int i = idx >> 7;
        g_globals[idx] = (g_cnt_i[i] > 0) ? funkey(g_gkeys[idx]) : 0.f;
    }
    if (idx < I * 3) {
        int i = idx / 3, d = idx % 3;
        g_gtlc[idx] = g_centroid[ils[i] * 3 + d];
    }
}

// ---------------- locals MLP on tensor cores (262->128 relu ->128 relu) + decoder ----------------
#define KF 262
#define KP 272
#define STRL 280
#define SH_MLP2 (2 * 128 * STRL * 2 + (128 + 128 + 1024 + 8) * 4 + 128 * 4)

__global__ __launch_bounds__(256) void k_mlp2(
    const float* __restrict__ b1, const float* __restrict__ b2,
    const float* __restrict__ Wd, const float* __restrict__ bd,
    const int* __restrict__ i2l,
    float* __restrict__ out_tf, float* __restrict__ out_fo, int L)
{
    extern __shared__ char smraw[];
    __half* A1 = (__half*)smraw;                         // [128][STRL]
    __half* B1 = (__half*)(smraw + 128 * STRL * 2);      // [128][STRL]
    float*  ext = (float*)(smraw + 2 * 128 * STRL * 2);
    float* b1L = ext;           // 128
    float* b2L = ext + 128;     // 128
    float* wdS = ext + 256;     // [c][8]
    float* bdS = ext + 1280;    // 8
    int*   ilS = (int*)(ext + 1288);
    __half* hA2 = (__half*)smraw;                        // [128][136] (phase 2)
    __half* W2s = (__half*)(smraw + 128 * STRL * 2);     // [128][136] (phase 2)
    float*  foS = (float*)smraw;                         // [128][133] (phase 3)

    int tid = threadIdx.x;
    int block0 = blockIdx.x * 128;

    if (tid < 128) {
        b1L[tid] = b1[tid];
        b2L[tid] = b2[tid];
        int l = block0 + tid;
        ilS[tid] = (l < L) ? i2l[l] : 0;
    }
    for (int idx = tid; idx < 128 * 7; idx += 256)
        wdS[(idx / 7) * 8 + (idx % 7)] = Wd[idx];
    if (tid < 7) bdS[tid] = bd[tid];
    __syncthreads();

    // assemble feat fp16 into A1[p][k], copy W1lt into B1[h][k]
    for (int idx = tid; idx < 128 * KP; idx += 256) {
        int p = idx / KP, k = idx - p * KP;
        int l = block0 + p;
        float v = 0.f;
        if (l < L && k < KF) {
            int inst = ilS[p];
            if (k < 128)       v = g_locals_feat[(size_t)l * CC + k];
            else if (k < 256)  v = g_globals[(size_t)inst * CC + (k - 128)];
            else if (k < 259)  v = g_centroid[l * 3 + (k - 256)];
            else               v = g_gtlc[inst * 3 + (k - 259)];
        }
        A1[p * STRL + k] = __float2half(v);
    }
    {
        const unsigned* src = (const unsigned*)g_W1lt;   // [h][272] as pairs
        for (int i = tid; i < 128 * (KP / 2); i += 256) {
            int h = i / (KP / 2), k2 = (i - h * (KP / 2)) << 1;
            *(unsigned*)&B1[h * STRL + k2] = src[i];
        }
    }
    __syncthreads();

    int wid = tid >> 5, lane = tid & 31;
    int m0 = (wid >> 1) * 32, n0 = (wid & 1) * 64;
    int g = lane >> 2, t4 = (lane & 3) * 2;

    uint32_t A1_s = (uint32_t)__cvta_generic_to_shared(A1);
    uint32_t B1_s = (uint32_t)__cvta_generic_to_shared(B1);
    uint32_t aOff = ((m0 + (lane & 15)) * STRL + ((lane >> 4) << 3)) * 2;
    uint32_t bOff = ((n0 + ((lane >> 4) << 3) + (lane & 7)) * STRL + (((lane >> 3) & 1) << 3)) * 2;

    float acc[2][8][4];
    #pragma unroll
    for (int a = 0; a < 2; a++)
        #pragma unroll
        for (int b_ = 0; b_ < 8; b_++)
            #pragma unroll
            for (int c = 0; c < 4; c++) acc[a][b_][c] = 0.f;

    // GEMM1: [128 x 128] = A1[128 x 272] * W1lt^T, K=272
    #pragma unroll
    for (int kk = 0; kk < KP; kk += 16) {
        unsigned af[2][4];
        ldm_x4(af[0], A1_s + aOff + kk * 2);
        ldm_x4(af[1], A1_s + aOff + kk * 2 + 16 * STRL * 2);
        #pragma unroll
        for (int np = 0; np < 4; np++) {
            unsigned bf[4];
            ldm_x4(bf, B1_s + bOff + kk * 2 + np * 16 * STRL * 2);
            mma16816(acc[0][2*np],   af[0], bf[0], bf[1]);
            mma16816(acc[1][2*np],   af[1], bf[0], bf[1]);
            mma16816(acc[0][2*np+1], af[0], bf[2], bf[3]);
            mma16816(acc[1][2*np+1], af[1], bf[2], bf[3]);
        }
    }
    __syncthreads();  // A1/B1 reads done -> reuse regions

    // epilogue 1: relu(acc + b1) -> hA2[p][h] fp16; copy W2lt into W2s
    #pragma unroll
    for (int mt = 0; mt < 2; mt++) {
        #pragma unroll
        for (int nt = 0; nt < 8; nt++) {
            int r0 = m0 + mt * 16 + g;
            int c = n0 + nt * 8 + t4;
            float h00 = fmaxf(acc[mt][nt][0] + b1L[c], 0.f);
            float h01 = fmaxf(acc[mt][nt][1] + b1L[c + 1], 0.f);
            float h10 = fmaxf(acc[mt][nt][2] + b1L[c], 0.f);
            float h11 = fmaxf(acc[mt][nt][3] + b1L[c + 1], 0.f);
            *(__half2*)&hA2[r0 * STRH + c] = __floats2half2_rn(h00, h01);
            *(__half2*)&hA2[(r0 + 8) * STRH + c] = __floats2half2_rn(h10, h11);
        }
    }
    {
        const unsigned* src = (const unsigned*)g_W2lt;
        for (int i = tid; i < 8192; i += 256) {
            int c = i >> 6, k2 = (i & 63) << 1;
            *(unsigned*)&W2s[c * STRH + k2] = src[i];
        }
    }
    __syncthreads();

    // GEMM2: [128 x 128] = hA2[128 x 128] * W2lt^T, K=128
    #pragma unroll
    for (int a = 0; a < 2; a++)
        #pragma unroll
        for (int b_ = 0; b_ < 8; b_++)
            #pragma unroll
            for (int c = 0; c < 4; c++) acc[a][b_][c] = 0.f;

    uint32_t hA2_s = (uint32_t)__cvta_generic_to_shared(hA2);
    uint32_t W2s_s = (uint32_t)__cvta_generic_to_shared(W2s);
    uint32_t aOff2 = ((m0 + (lane & 15)) * STRH + ((lane >> 4) << 3)) * 2;
    uint32_t bOff2 = ((n0 + ((lane >> 4) << 3) + (lane & 7)) * STRH + (((lane >> 3) & 1) << 3)) * 2;

    #pragma unroll
    for (int kk = 0; kk < 128; kk += 16) {
        unsigned af[2][4];
        ldm_x4(af[0], hA2_s + aOff2 + kk * 2);
        ldm_x4(af[1], hA2_s + aOff2 + kk * 2 + 16 * STRH * 2);
        #pragma unroll
        for (int np = 0; np < 4; np++) {
            unsigned bf[4];
            ldm_x4(bf, W2s_s + bOff2 + kk * 2 + np * 16 * STRH * 2);
            mma16816(acc[0][2*np],   af[0], bf[0], bf[1]);
            mma16816(acc[1][2*np],   af[1], bf[0], bf[1]);
            mma16816(acc[0][2*np+1], af[0], bf[2], bf[3]);
            mma16816(acc[1][2*np+1], af[1], bf[2], bf[3]);
        }
    }
    __syncthreads();  // hA2/W2s reads done -> reuse as foS

    // epilogue 2: relu(acc + b2) -> out_fo (global) + foS (smem, f32)
    #pragma unroll
    for (int mt = 0; mt < 2; mt++) {
        #pragma unroll
        for (int nt = 0; nt < 8; nt++) {
            int r0 = m0 + mt * 16 + g;
            int c = n0 + nt * 8 + t4;
            float v00 = fmaxf(acc[mt][nt][0] + b2L[c], 0.f);
            float v01 = fmaxf(acc[mt][nt][1] + b2L[c + 1], 0.f);
            float v10 = fmaxf(acc[mt][nt][2] + b2L[c], 0.f);
            float v11 = fmaxf(acc[mt][nt][3] + b2L[c + 1], 0.f);
            foS[r0 * 133 + c] = v00; foS[r0 * 133 + c + 1] = v01;
            foS[(r0 + 8) * 133 + c] = v10; foS[(r0 + 8) * 133 + c + 1] = v11;
            int l0 = block0 + r0, l1 = block0 + r0 + 8;
            if (l0 < L) { float2 s; s.x = v00; s.y = v01; *(float2*)&out_fo[(size_t)l0 * CC + c] = s; }
            if (l1 < L) { float2 s; s.x = v10; s.y = v11; *(float2*)&out_fo[(size_t)l1 * CC + c] = s; }
        }
    }
    __syncthreads();

    // decoder: 128 threads, one local each, 7 outputs
    if (tid < 128) {
        int l = block0 + tid;
        if (l < L) {
            float s[7];
            #pragma unroll
            for (int j = 0; j < 7; j++) s[j] = bdS[j];
            for (int c = 0; c < 128; c++) {
                float f = foS[tid * 133 + c];
                #pragma unroll
                for (int j = 0; j < 7; j++) s[j] = fmaf(f, wdS[c * 8 + j], s[j]);
            }
            #pragma unroll
            for (int j = 0; j < 7; j++) out_tf[(size_t)l * 7 + j] = s[j];
        }
    }
}

// ---------------- launch ----------------
extern "C" void kernel_launch(void* const* d_in, const int* in_sizes, int n_in,
                              void* d_out, int out_size) {
    const float* xyz  = (const float*)d_in[0];
    const float* feat = (const float*)d_in[1];
    const float* W1s_ = (const float*)d_in[2];
    const float* b1s_ = (const float*)d_in[3];
    const float* W2s_ = (const float*)d_in[4];
    const float* b2s_ = (const float*)d_in[5];
    const float* W1l  = (const float*)d_in[6];
    const float* b1l  = (const float*)d_in[7];
    const float* W2l  = (const float*)d_in[8];
    const float* b2l  = (const float*)d_in[9];
    const float* Wd   = (const float*)d_in[10];
    const float* bd   = (const float*)d_in[11];
    const int*   l2f  = (const int*)d_in[12];
    const int*   i2l  = (const int*)d_in[13];
    const int*   ils  = (const int*)d_in[14];

    int n = in_sizes[0] / 3;
    int L = in_sizes[13];
    int I = in_sizes[14];

    float* out_tf = (float*)d_out;
    float* out_fo = (float*)d_out + (size_t)L * 7;

    cudaFuncSetAttribute(k_shape, cudaFuncAttributeMaxDynamicSharedMemorySize, SH_SHAPE);
    cudaFuncSetAttribute(k_mlp2,  cudaFuncAttributeMaxDynamicSharedMemorySize, SH_MLP2);

    k_init<<<(L * CC + 255) / 256, 256>>>(L, I);
    k_prep<<<64, 256>>>(W2s_);
    k_prep2<<<(128 * 272 + 255) / 256, 256>>>(W1l, W2l);
    k_count<<<(n + 255) / 256, 256>>>(xyz, l2f, n);
    k_centroid<<<(L + 255) / 256, 256>>>(L);
    k_scan<<<1, 1024>>>(L);
    k_csr<<<(n + 255) / 256, 256>>>(l2f, n);
    k_shape<<<(n + 127) / 128, 256, SH_SHAPE>>>(xyz, W1s_, b1s_, b2s_, n);
    k_featmax<<<(L * 32 + 255) / 256, 256>>>(feat, i2l, L);
    k_gfin<<<(I * CC + 255) / 256, 256>>>(ils, I);
    k_mlp2<<<(L + 127) / 128, 256, SH_MLP2>>>(b1l, b2l, Wd, bd, i2l, out_tf, out_fo, L);
}